// round 14
// baseline (speedup 1.0000x reference)
#include <cuda_runtime.h>
#include <cuda_bf16.h>
#include <cstdint>

// Problem constants
#define QN      4
#define KCODES  512
#define DDIM    256
#define HH      1024
#define WW      4
#define BB      16
#define TILE_H  32
#define ROWS    128
#define NROWS   65536
#define NCTA    512
#define NTHR    256
#define CTILE   64        // codes per B tile
#define NTILE   8         // KCODES/CTILE

#define IDX_OFF   (NROWS*DDIM)
#define LOSS_OFF  (IDX_OFF + NROWS*QN)

// smem layout (bytes). Row stride 528B = 132 words (33 uint4): ldmatrix phases
// read 8 rows starting at banks {4r mod 32} -> conflict-free.
#define RSTR  528
#define BHALF 33792                    // 64 codes * 528
#define BBUF  67584                    // hi + lo
#define OFF_ALO  0
#define OFF_B    67584                 // two buffers of BBUF (also A_hi temp / x stage)
#define OFF_CN   202752
#define OFF_R2   204800
#define OFF_CAND 205312
#define OFF_DC   206336
#define OFF_SIDX 207360
#define OFF_RSUM 207872
#define OFF_LAST 208384
#define SMEM_BYTES (OFF_LAST + 16)

__device__ float g_norms[QN*KCODES];
__device__ float g_loss_part[NCTA][QN];
__device__ int   g_done = 0;
__device__ float g_resid[(long)NROWS * DDIM];            // 64MB residual scratch
__device__ uint4 g_cbh4[QN*KCODES*DDIM/8];               // bf16 hi codebook (1MB)
__device__ uint4 g_cbl4[QN*KCODES*DDIM/8];               // bf16 lo codebook (1MB)

__device__ __forceinline__ uint32_t smem_to_u32(const void* p) {
    uint32_t a;
    asm("{ .reg .u64 t; cvta.to.shared.u64 t, %1; cvt.u32.u64 %0, t; }" : "=r"(a) : "l"(p));
    return a;
}
#define CP_ASYNC16(dst, src) \
    asm volatile("cp.async.cg.shared.global [%0], [%1], 16;" :: "r"(dst), "l"(src))
#define CP_COMMIT() asm volatile("cp.async.commit_group;" ::: "memory")
#define CP_WAIT0()  asm volatile("cp.async.wait_group 0;" ::: "memory")

#define LDSM_X4(r0, r1, r2, r3, addr) \
    asm volatile("ldmatrix.sync.aligned.m8n8.x4.shared.b16 {%0,%1,%2,%3}, [%4];" \
        : "=r"(r0), "=r"(r1), "=r"(r2), "=r"(r3) : "r"(addr))

// m16n8k16 bf16 MMA (sm_80+ baseline instruction)
__device__ __forceinline__ void mma16816(float* d, uint32_t a0, uint32_t a1,
                                         uint32_t a2, uint32_t a3,
                                         uint32_t b0, uint32_t b1) {
    asm volatile(
        "mma.sync.aligned.m16n8k16.row.col.f32.bf16.bf16.f32 "
        "{%0,%1,%2,%3}, {%4,%5,%6,%7}, {%8,%9}, {%0,%1,%2,%3};"
        : "+f"(d[0]), "+f"(d[1]), "+f"(d[2]), "+f"(d[3])
        : "r"(a0), "r"(a1), "r"(a2), "r"(a3), "r"(b0), "r"(b1));
}

__device__ __forceinline__ void upd2(float &b0, int &i0, float &b1, int &i1,
                                     float sc, int gi) {
    if (sc < b0 || (sc == b0 && gi < i0)) { b1 = b0; i1 = i0; b0 = sc; i0 = gi; }
    else if (sc < b1 || (sc == b1 && gi < i1)) { b1 = sc; i1 = gi; }
}

// pack 8 floats -> 8 bf16 (comp 0 = hi, 1 = lo residue)
__device__ __forceinline__ uint4 pack8(const float4 &v0, const float4 &v1, int comp) {
    float f[8] = {v0.x, v0.y, v0.z, v0.w, v1.x, v1.y, v1.z, v1.w};
    unsigned short u[8];
    #pragma unroll
    for (int i = 0; i < 8; ++i) {
        __nv_bfloat16 h = __float2bfloat16(f[i]);
        if (comp) h = __float2bfloat16(f[i] - __bfloat162float(h));
        u[i] = __bfloat16_as_ushort(h);
    }
    uint4 o;
    o.x = (uint32_t)u[0] | ((uint32_t)u[1] << 16);
    o.y = (uint32_t)u[2] | ((uint32_t)u[3] << 16);
    o.z = (uint32_t)u[4] | ((uint32_t)u[5] << 16);
    o.w = (uint32_t)u[6] | ((uint32_t)u[7] << 16);
    return o;
}

// ---------------- prep: code norms (FROZEN XLA order) + bf16 hi/lo split ----------------
__global__ void rvq_prep_kernel(const float* __restrict__ cb) {
    int gtid = blockIdx.x * blockDim.x + threadIdx.x;
    {
        int warp = gtid >> 5;
        int lane = threadIdx.x & 31;
        if (warp < QN * KCODES) {
            const float* row = cb + (long)warp * DDIM;
            float s = 0.f;
            #pragma unroll
            for (int i = 0; i < 8; ++i) {
                float v = __ldg(&row[lane + 32 * i]);
                s = __fadd_rn(s, __fmul_rn(v, v));
            }
            #pragma unroll
            for (int off = 16; off >= 1; off >>= 1)
                s = __fadd_rn(s, __shfl_down_sync(0xffffffffu, s, off));
            if (lane == 0) g_norms[warp] = s;
        }
    }
    if (gtid < QN * KCODES * DDIM / 8) {
        const float4* src = reinterpret_cast<const float4*>(cb) + gtid * 2;
        float4 v0 = __ldg(&src[0]);
        float4 v1 = __ldg(&src[1]);
        g_cbh4[gtid] = pack8(v0, v1, 0);
        g_cbl4[gtid] = pack8(v0, v1, 1);
    }
}

// ---------------- main fused RVQ (ldmatrix/HMMA scan + FROZEN exact paths) ----------------
__global__ __launch_bounds__(NTHR, 1)
void rvq_main_kernel(const float* __restrict__ x, const float* __restrict__ cb,
                     float* __restrict__ out, int out_size) {
    extern __shared__ char smem[];
    const uint32_t smem_base = smem_to_u32(smem);
    const int tid  = threadIdx.x;
    const int wid  = tid >> 5;
    const int lane = tid & 31;
    const int gid  = lane >> 2;    // 0..7
    const int tk   = lane & 3;     // 0..3
    const int m0   = wid * 16;     // warp's row block
    const int cta  = blockIdx.x;
    const int b    = cta >> 5;
    const int h0   = (cta & 31) * TILE_H;
    const long rb  = (long)cta * ROWS * DDIM;

    float* Scn   = reinterpret_cast<float*>(smem + OFF_CN);
    float* Sr2   = reinterpret_cast<float*>(smem + OFF_R2);
    int*   Scand = reinterpret_cast<int*>(smem + OFF_CAND);   // [2][128]
    float* Sdc   = reinterpret_cast<float*>(smem + OFF_DC);   // [2][128]
    int*   Ssidx = reinterpret_cast<int*>(smem + OFF_SIDX);
    float* Srsum = reinterpret_cast<float*>(smem + OFF_RSUM);
    int*   Slast = reinterpret_cast<int*>(smem + OFF_LAST);

    // ldmatrix source addresses (per-thread constants)
    const uint32_t frag_row  = (lane & 15);
    const uint32_t frag_koff = ((lane >> 4) & 1) * 16;
    const uint32_t brow      = ((lane >> 4) & 1) * 8 + (lane & 7);
    const uint32_t bkoff     = ((lane >> 3) & 1) * 16;

    // ---- init residual = gathered x, staged through smem ----
    {
        float* stage = reinterpret_cast<float*>(smem);   // [256][128] at offset 0
        const float4* x4 = reinterpret_cast<const float4*>(x);
        for (int t = tid; t < DDIM * 32; t += NTHR) {
            int c = t >> 5, f4c = t & 31;
            float4 v = __ldg(&x4[((long)(b * DDIM + c)) * HH + h0 + f4c]);
            float* d = &stage[c * ROWS + f4c * 4];
            d[0] = v.x; d[1] = v.y; d[2] = v.z; d[3] = v.w;
        }
        __syncthreads();
        int lr = tid >> 1, half = tid & 1;
        for (int k0 = half * 128; k0 < half * 128 + 128; k0 += 4) {
            float4 o = make_float4(stage[(k0+0)*ROWS+lr], stage[(k0+1)*ROWS+lr],
                                   stage[(k0+2)*ROWS+lr], stage[(k0+3)*ROWS+lr]);
            *reinterpret_cast<float4*>(&g_resid[rb + (long)lr * DDIM + k0]) = o;
        }
        __syncthreads();
    }

    const bool write_idx = (out_size >= IDX_OFF + NROWS * QN);

    for (int q = 0; q < QN; ++q) {
        // ---- ||r||^2, XLA-GPU order (FROZEN), warp-per-row ----
        #pragma unroll
        for (int pass = 0; pass < 16; ++pass) {
            int row = pass * 8 + wid;
            const float* rr = &g_resid[rb + (long)row * DDIM];
            float s = 0.f;
            #pragma unroll
            for (int i = 0; i < 8; ++i) {
                float v = rr[lane + 32 * i];
                s = __fadd_rn(s, __fmul_rn(v, v));
            }
            #pragma unroll
            for (int off = 16; off >= 1; off >>= 1)
                s = __fadd_rn(s, __shfl_down_sync(0xffffffffu, s, off));
            if (lane == 0) Sr2[row] = s;
        }

        // ---- pack A_lo -> OFF_ALO; A_hi -> OFF_B (temp) ----
        {
            int r = tid >> 1, half = tid & 1;
            uint4* dAl = reinterpret_cast<uint4*>(smem + OFF_ALO);
            uint4* dAh = reinterpret_cast<uint4*>(smem + OFF_B);
            #pragma unroll
            for (int k0 = half * 128; k0 < half * 128 + 128; k0 += 8) {
                const float4* src = reinterpret_cast<const float4*>(
                    &g_resid[rb + (long)r * DDIM + k0]);
                float4 v0 = src[0], v1 = src[1];
                int di = r * 33 + (k0 >> 3);
                dAh[di] = pack8(v0, v1, 0);
                dAl[di] = pack8(v0, v1, 1);
            }
        }
        for (int i = tid; i < KCODES; i += NTHR) Scn[i] = g_norms[q * KCODES + i];
        __syncthreads();

        // ---- load persistent A_hi fragments from temp (64 regs) ----
        uint32_t ahi[16][4];
        {
            uint32_t abase = smem_base + OFF_B + frag_row * RSTR + frag_koff;
            #pragma unroll
            for (int ks = 0; ks < 16; ++ks)
                LDSM_X4(ahi[ks][0], ahi[ks][1], ahi[ks][2], ahi[ks][3],
                        abase + m0 * RSTR + ks * 32);
        }
        __syncthreads();   // temp free; B buffers may now be written

        // prefetch B tile 0 into buffer 0
        {
            const uint4* srcH = &g_cbh4[(long)(q * KCODES) * 32];
            const uint4* srcL = &g_cbl4[(long)(q * KCODES) * 32];
            uint32_t d0 = smem_base + OFF_B;
            #pragma unroll
            for (int it = 0; it < 16; ++it) {
                int i = tid + it * NTHR;        // 4096 chunks: [comp][code][kc]
                int comp = i >> 11, r = (i >> 5) & 63, kc = i & 31;
                const uint4* s = comp ? &srcL[r * 32 + kc] : &srcH[r * 32 + kc];
                CP_ASYNC16(d0 + comp * BHALF + (r * 33 + kc) * 16, s);
            }
            CP_COMMIT();
        }

        // per-thread top-2 for rows rA = m0+gid, rB = rA+8
        float b0A = 3.4e38f, b1A = 3.4e38f, b0B = 3.4e38f, b1B = 3.4e38f;
        int   i0A = 0x7fffffff, i1A = 0x7fffffff, i0B = 0x7fffffff, i1B = 0x7fffffff;

        for (int ct = 0; ct < NTILE; ++ct) {
            CP_WAIT0();
            __syncthreads();   // tile ct arrived everywhere; prev compute done

            if (ct + 1 < NTILE) {
                const uint4* srcH = &g_cbh4[(long)(q * KCODES + (ct + 1) * CTILE) * 32];
                const uint4* srcL = &g_cbl4[(long)(q * KCODES + (ct + 1) * CTILE) * 32];
                uint32_t d0 = smem_base + OFF_B + ((ct + 1) & 1) * BBUF;
                #pragma unroll
                for (int it = 0; it < 16; ++it) {
                    int i = tid + it * NTHR;
                    int comp = i >> 11, r = (i >> 5) & 63, kc = i & 31;
                    const uint4* s = comp ? &srcL[r * 32 + kc] : &srcH[r * 32 + kc];
                    CP_ASYNC16(d0 + comp * BHALF + (r * 33 + kc) * 16, s);
                }
                CP_COMMIT();
            }

            const uint32_t bh_base = smem_base + OFF_B + (ct & 1) * BBUF
                                     + brow * RSTR + bkoff;
            const uint32_t al_base = smem_base + OFF_ALO + (m0 + frag_row) * RSTR
                                     + frag_koff;

            float acc[8][4];
            #pragma unroll
            for (int j = 0; j < 8; ++j)
                #pragma unroll
                for (int v = 0; v < 4; ++v) acc[j][v] = 0.f;

            #pragma unroll
            for (int ks = 0; ks < 16; ++ks) {
                // load A_lo frag + ALL B fragments for this k-step up front
                uint32_t al[4];
                LDSM_X4(al[0], al[1], al[2], al[3], al_base + ks * 32);
                uint32_t bh[4][4], bl[4][4];
                #pragma unroll
                for (int p = 0; p < 4; ++p) {
                    uint32_t ba = bh_base + p * 16 * RSTR + ks * 32;
                    LDSM_X4(bh[p][0], bh[p][1], bh[p][2], bh[p][3], ba);
                    LDSM_X4(bl[p][0], bl[p][1], bl[p][2], bl[p][3], ba + BHALF);
                }
                // pass-major issue: 8 independent MMAs per pass -> chain distance 8
                // (per-acc order hh, hl, lh preserved => identical accumulation)
                #pragma unroll
                for (int p = 0; p < 4; ++p) {
                    mma16816(acc[2*p],   ahi[ks][0], ahi[ks][1], ahi[ks][2], ahi[ks][3], bh[p][0], bh[p][1]);
                    mma16816(acc[2*p+1], ahi[ks][0], ahi[ks][1], ahi[ks][2], ahi[ks][3], bh[p][2], bh[p][3]);
                }
                #pragma unroll
                for (int p = 0; p < 4; ++p) {
                    mma16816(acc[2*p],   ahi[ks][0], ahi[ks][1], ahi[ks][2], ahi[ks][3], bl[p][0], bl[p][1]);
                    mma16816(acc[2*p+1], ahi[ks][0], ahi[ks][1], ahi[ks][2], ahi[ks][3], bl[p][2], bl[p][3]);
                }
                #pragma unroll
                for (int p = 0; p < 4; ++p) {
                    mma16816(acc[2*p],   al[0], al[1], al[2], al[3], bh[p][0], bh[p][1]);
                    mma16816(acc[2*p+1], al[0], al[1], al[2], al[3], bh[p][2], bh[p][3]);
                }
            }

            // scores + top-2 (selection only; frozen rescore fixes exact values)
            #pragma unroll
            for (int j = 0; j < 8; ++j) {
                int c0 = ct * CTILE + j * 8 + tk * 2;
                float n0 = Scn[c0], n1 = Scn[c0 + 1];
                upd2(b0A, i0A, b1A, i1A, fmaf(-2.f, acc[j][0], n0), c0);
                upd2(b0A, i0A, b1A, i1A, fmaf(-2.f, acc[j][1], n1), c0 + 1);
                upd2(b0B, i0B, b1B, i1B, fmaf(-2.f, acc[j][2], n0), c0);
                upd2(b0B, i0B, b1B, i1B, fmaf(-2.f, acc[j][3], n1), c0 + 1);
            }
        }

        // merge top-2 across the 4 tk-lanes of each row
        #pragma unroll
        for (int off = 1; off <= 2; off <<= 1) {
            float ob0A = __shfl_xor_sync(0xffffffffu, b0A, off);
            int   oi0A = __shfl_xor_sync(0xffffffffu, i0A, off);
            float ob1A = __shfl_xor_sync(0xffffffffu, b1A, off);
            int   oi1A = __shfl_xor_sync(0xffffffffu, i1A, off);
            float ob0B = __shfl_xor_sync(0xffffffffu, b0B, off);
            int   oi0B = __shfl_xor_sync(0xffffffffu, i0B, off);
            float ob1B = __shfl_xor_sync(0xffffffffu, b1B, off);
            int   oi1B = __shfl_xor_sync(0xffffffffu, i1B, off);
            upd2(b0A, i0A, b1A, i1A, ob0A, oi0A);
            upd2(b0A, i0A, b1A, i1A, ob1A, oi1A);
            upd2(b0B, i0B, b1B, i1B, ob0B, oi0B);
            upd2(b0B, i0B, b1B, i1B, ob1B, oi1B);
        }
        if (tk == 0) {
            int rA = m0 + gid;
            Scand[rA]       = i0A;  Scand[128 + rA]     = i1A;
            Scand[rA + 8]   = i0B;  Scand[128 + rA + 8] = i1B;
        }
        __syncthreads();

        // ---- rescore top-2, cuBLAS-SGEMM arithmetic (FROZEN) ----
        {
            int row = tid >> 1, c = tid & 1;
            int idx = Scand[c * 128 + row];
            const float2* rr = reinterpret_cast<const float2*>(&g_resid[rb + (long)row * DDIM]);
            const float2* crow = reinterpret_cast<const float2*>(
                cb + ((long)(q * KCODES + idx)) * DDIM);
            float acc = 0.f;
            #pragma unroll 8
            for (int kk = 0; kk < 128; ++kk) {
                float2 r = rr[kk];
                float2 cv = __ldg(&crow[kk]);
                acc = fmaf(r.x, cv.x, acc);
                acc = fmaf(r.y, cv.y, acc);
            }
            float tt = __fsub_rn(Sr2[row], __fmul_rn(2.f, acc));
            Sdc[c * 128 + row] = __fadd_rn(tt, g_norms[q * KCODES + idx]);
        }
        __syncthreads();
        if (tid < ROWS) {
            float d0 = Sdc[tid], d1 = Sdc[128 + tid];
            int i0 = Scand[tid], i1 = Scand[128 + tid];
            Ssidx[tid] = (d1 < d0 || (d1 == d0 && i1 < i0)) ? i1 : i0;
        }
        __syncthreads();

        // ---- residual update (exact fp32, FROZEN) ----
        {
            int lr = tid >> 1, half = tid & 1;
            int idx = Ssidx[lr];
            const float4* crow = reinterpret_cast<const float4*>(
                cb + ((long)(q * KCODES + idx)) * DDIM);
            float4* rr = reinterpret_cast<float4*>(&g_resid[rb + (long)lr * DDIM]);
            #pragma unroll
            for (int f4 = half * 32; f4 < half * 32 + 32; ++f4) {
                float4 v = __ldg(&crow[f4]);
                float4 a = rr[f4];
                a.x -= v.x; a.y -= v.y; a.z -= v.z; a.w -= v.w;
                rr[f4] = a;
            }
        }
        if (write_idx && tid < ROWS) {
            int w = tid & 3, hh = tid >> 2;
            long n = ((long)(b * WW + w)) * HH + h0 + hh;
            out[IDX_OFF + n * QN + q] = (float)Ssidx[tid];
        }
        __syncthreads();

        // ---- loss: serial fmaf per row (FROZEN), fixed-order CTA sum ----
        if (tid < ROWS) {
            const float2* rr = reinterpret_cast<const float2*>(&g_resid[rb + (long)tid * DDIM]);
            float s = 0.f;
            #pragma unroll 8
            for (int kk = 0; kk < 128; ++kk) {
                float2 v = rr[kk];
                s = fmaf(v.x, v.x, s);
                s = fmaf(v.y, v.y, s);
            }
            Srsum[tid] = s;
        }
        __syncthreads();
        if (tid == 0) {
            float s = 0.f;
            #pragma unroll
            for (int i = 0; i < ROWS; ++i) s += Srsum[i];
            g_loss_part[cta][q] = s;
        }
        __syncthreads();
    }

    // ---- quantized_out = x - residual_final (exact fp32) ----
    {
        int lr = tid & 127, ks = tid >> 7;
        int w = lr & 3, hh = lr >> 2;
        long n = ((long)(b * WW + w)) * HH + h0 + hh;
        float4* orow = reinterpret_cast<float4*>(out + n * DDIM);
        const float4* rr = reinterpret_cast<const float4*>(&g_resid[rb + (long)lr * DDIM]);
        long cbase = (((long)b * DDIM) * HH + (h0 + hh)) * WW + w;
        #pragma unroll
        for (int f4 = ks * 32; f4 < ks * 32 + 32; ++f4) {
            int c0 = f4 * 4;
            float x0 = __ldg(&x[cbase + (long)(c0 + 0) * (HH * WW)]);
            float x1 = __ldg(&x[cbase + (long)(c0 + 1) * (HH * WW)]);
            float x2 = __ldg(&x[cbase + (long)(c0 + 2) * (HH * WW)]);
            float x3 = __ldg(&x[cbase + (long)(c0 + 3) * (HH * WW)]);
            float4 r = rr[f4];
            orow[f4] = make_float4(x0 - r.x, x1 - r.y, x2 - r.z, x3 - r.w);
        }
    }

    // ---- fused loss finalize: last CTA (fixed-order, FROZEN) ----
    __threadfence();
    __syncthreads();
    if (tid == 0) {
        int old = atomicAdd(&g_done, 1);
        *Slast = (old == (int)gridDim.x - 1) ? 1 : 0;
    }
    __syncthreads();
    if (*Slast) {
        if (out_size >= LOSS_OFF + QN && tid < 128) {
            int q = tid >> 5, ln = tid & 31;
            float s = 0.f;
            for (int i = ln; i < NCTA; i += 32) s += g_loss_part[i][q];
            #pragma unroll
            for (int off = 16; off; off >>= 1)
                s += __shfl_xor_sync(0xffffffffu, s, off);
            if (ln == 0) out[LOSS_OFF + q] = s / (float)(NROWS * DDIM);
        }
        if (tid == 0) g_done = 0;
    }
}

extern "C" void kernel_launch(void* const* d_in, const int* in_sizes, int n_in,
                              void* d_out, int out_size) {
    const float* x  = (const float*)d_in[0];
    const float* cb = (const float*)d_in[1];
    float* out = (float*)d_out;

    cudaFuncSetAttribute(rvq_main_kernel,
                         cudaFuncAttributeMaxDynamicSharedMemorySize, (int)SMEM_BYTES);

    rvq_prep_kernel<<<(QN*KCODES*32 + 255)/256, 256>>>(cb);
    rvq_main_kernel<<<NCTA, NTHR, SMEM_BYTES>>>(x, cb, out, out_size);
}